// round 1
// baseline (speedup 1.0000x reference)
#include <cuda_runtime.h>
#include <math.h>

// Problem constants (fixed by the dataset)
#define Bn   8
#define HWn  4096
#define Dn   256
#define LWn  1024
#define NWn  32      // b * ns * ns
#define DHn  2048    // MLP hidden
#define Mtot (Bn*HWn)  // 32768 rows

// ---- scratch (device globals; no allocation allowed) ----
__device__ float g_q  [(size_t)Bn*HWn*Dn];
__device__ float g_k  [(size_t)Bn*HWn*Dn];
__device__ float g_v  [(size_t)Bn*HWn*Dn];
__device__ float g_sc [(size_t)NWn*LWn*LWn];   // 134 MB scores
__device__ float g_msg[(size_t)Bn*HWn*Dn];
__device__ float g_tmp[(size_t)Bn*HWn*Dn];
__device__ float g_hid[(size_t)Bn*HWn*DHn];    // 268 MB

// window-token <-> original-token permutation (roll(-16,-16) + 2x2 window split)
__device__ __forceinline__ int win_tok(int wi, int l) {
    int i = l >> 5, j = l & 31;
    int y = (((wi >> 1) << 5) + i + 16) & 63;
    int x = (((wi &  1) << 5) + j + 16) & 63;
    return (y << 6) | x;
}

// ======================================================================
// Generic tiled SGEMM:  C[M,N] = A[M,K] @ B[:,boff:boff+K]^T   (B row-major [N,ldb])
// 64x64 tile, BK=16, 256 threads, 4x4 microtile. Dims must divide tiles.
// ======================================================================
__global__ void gemm_nt(const float* __restrict__ A, const float* __restrict__ Bm,
                        float* __restrict__ C,
                        int M, int N, int K, int ldb, int boff, int accumulate)
{
    __shared__ float As[16][68];
    __shared__ float Bs[16][68];
    int t  = threadIdx.x;
    int tx = t & 15, ty = t >> 4;
    int row0 = blockIdx.y << 6;
    int col0 = blockIdx.x << 6;

    int ar = t >> 2;             // 0..63 tile row
    int ac = (t & 3) << 2;       // 0,4,8,12 k-offset
    const float* Arow = A  + (size_t)(row0 + ar) * K;
    const float* Brow = Bm + (size_t)(col0 + ar) * ldb + boff;

    float acc[4][4] = {};
    for (int k0 = 0; k0 < K; k0 += 16) {
        float4 av = *(const float4*)(Arow + k0 + ac);
        float4 bv = *(const float4*)(Brow + k0 + ac);
        As[ac+0][ar]=av.x; As[ac+1][ar]=av.y; As[ac+2][ar]=av.z; As[ac+3][ar]=av.w;
        Bs[ac+0][ar]=bv.x; Bs[ac+1][ar]=bv.y; Bs[ac+2][ar]=bv.z; Bs[ac+3][ar]=bv.w;
        __syncthreads();
        #pragma unroll
        for (int kk = 0; kk < 16; kk++) {
            float4 a = *(const float4*)&As[kk][ty << 2];
            float4 b = *(const float4*)&Bs[kk][tx << 2];
            float aa[4] = {a.x, a.y, a.z, a.w};
            float bb[4] = {b.x, b.y, b.z, b.w};
            #pragma unroll
            for (int i = 0; i < 4; i++)
                #pragma unroll
                for (int j = 0; j < 4; j++)
                    acc[i][j] += aa[i] * bb[j];
        }
        __syncthreads();
    }
    #pragma unroll
    for (int i = 0; i < 4; i++) {
        float* cp = C + (size_t)(row0 + (ty << 2) + i) * N + col0 + (tx << 2);
        float4 o = make_float4(acc[i][0], acc[i][1], acc[i][2], acc[i][3]);
        if (accumulate) {
            float4 old = *(float4*)cp;
            o.x += old.x; o.y += old.y; o.z += old.z; o.w += old.w;
        }
        *(float4*)cp = o;
    }
}

// ======================================================================
// scores[bw,l,s] = (1/16) * <q[b,tok(wi,l)], k[b,tok(wi,s)]> + mask[wi,l,s]
// ======================================================================
__global__ void scores_kernel(const float* __restrict__ q, const float* __restrict__ k,
                              const float* __restrict__ mask, float* __restrict__ sc)
{
    __shared__ float As[16][68];
    __shared__ float Bs[16][68];
    int bw = blockIdx.z, b = bw >> 2, wi = bw & 3;
    int t  = threadIdx.x;
    int tx = t & 15, ty = t >> 4;
    int row0 = blockIdx.y << 6;   // l
    int col0 = blockIdx.x << 6;   // s

    int ar = t >> 2;
    int ac = (t & 3) << 2;
    const float* Arow = q + (size_t)b*HWn*Dn + (size_t)win_tok(wi, row0 + ar) * Dn;
    const float* Brow = k + (size_t)b*HWn*Dn + (size_t)win_tok(wi, col0 + ar) * Dn;

    float acc[4][4] = {};
    for (int k0 = 0; k0 < Dn; k0 += 16) {
        float4 av = *(const float4*)(Arow + k0 + ac);
        float4 bv = *(const float4*)(Brow + k0 + ac);
        As[ac+0][ar]=av.x; As[ac+1][ar]=av.y; As[ac+2][ar]=av.z; As[ac+3][ar]=av.w;
        Bs[ac+0][ar]=bv.x; Bs[ac+1][ar]=bv.y; Bs[ac+2][ar]=bv.z; Bs[ac+3][ar]=bv.w;
        __syncthreads();
        #pragma unroll
        for (int kk = 0; kk < 16; kk++) {
            float4 a = *(const float4*)&As[kk][ty << 2];
            float4 b4 = *(const float4*)&Bs[kk][tx << 2];
            float aa[4] = {a.x, a.y, a.z, a.w};
            float bb[4] = {b4.x, b4.y, b4.z, b4.w};
            #pragma unroll
            for (int i = 0; i < 4; i++)
                #pragma unroll
                for (int j = 0; j < 4; j++)
                    acc[i][j] += aa[i] * bb[j];
        }
        __syncthreads();
    }
    const float scale = 0.0625f;  // 1/sqrt(256)
    #pragma unroll
    for (int i = 0; i < 4; i++) {
        int l = row0 + (ty << 2) + i;
        size_t so = (size_t)bw * LWn * LWn + (size_t)l * LWn + col0 + (tx << 2);
        size_t mo = (size_t)wi * LWn * LWn + (size_t)l * LWn + col0 + (tx << 2);
        float4 m4 = *(const float4*)&mask[mo];
        float4 o  = make_float4(acc[i][0]*scale + m4.x, acc[i][1]*scale + m4.y,
                                acc[i][2]*scale + m4.z, acc[i][3]*scale + m4.w);
        *(float4*)&sc[so] = o;
    }
}

// ======================================================================
// row softmax over 1024 elements (scores already include mask)
// ======================================================================
__global__ void softmax_kernel(float* __restrict__ s)
{
    __shared__ float red[256];
    size_t base = (size_t)blockIdx.x * LWn;
    int t = threadIdx.x;
    float4 v = *(const float4*)&s[base + (t << 2)];
    red[t] = fmaxf(fmaxf(v.x, v.y), fmaxf(v.z, v.w));
    __syncthreads();
    for (int st = 128; st > 0; st >>= 1) {
        if (t < st) red[t] = fmaxf(red[t], red[t + st]);
        __syncthreads();
    }
    float rm = red[0];
    __syncthreads();
    v.x = __expf(v.x - rm); v.y = __expf(v.y - rm);
    v.z = __expf(v.z - rm); v.w = __expf(v.w - rm);
    red[t] = v.x + v.y + v.z + v.w;
    __syncthreads();
    for (int st = 128; st > 0; st >>= 1) {
        if (t < st) red[t] += red[t + st];
        __syncthreads();
    }
    float inv = 1.0f / red[0];
    v.x *= inv; v.y *= inv; v.z *= inv; v.w *= inv;
    *(float4*)&s[base + (t << 2)] = v;
}

// ======================================================================
// out[b, tok(wi,l), c] = sum_s attn[bw,l,s] * v[b, tok(wi,s), c]
// (A@B form with gathered B rows and scattered output rows)
// ======================================================================
__global__ void attnv_kernel(const float* __restrict__ attn, const float* __restrict__ v,
                             float* __restrict__ out)
{
    __shared__ float As[16][68];   // [k][m]
    __shared__ float Bs[16][68];   // [k][n]
    int bw = blockIdx.z, b = bw >> 2, wi = bw & 3;
    int t  = threadIdx.x;
    int tx = t & 15, ty = t >> 4;
    int row0 = blockIdx.y << 6;   // l
    int col0 = blockIdx.x << 6;   // c

    int ar = t >> 2;
    int ac = (t & 3) << 2;
    int br = t >> 4;              // 0..15 (k row of B tile)
    int bc = (t & 15) << 2;       // 0..60
    const float* Arow = attn + (size_t)bw * LWn * LWn + (size_t)(row0 + ar) * LWn;
    const float* vb   = v + (size_t)b * HWn * Dn;

    float acc[4][4] = {};
    for (int k0 = 0; k0 < LWn; k0 += 16) {
        float4 av = *(const float4*)(Arow + k0 + ac);
        As[ac+0][ar]=av.x; As[ac+1][ar]=av.y; As[ac+2][ar]=av.z; As[ac+3][ar]=av.w;
        int tok = win_tok(wi, k0 + br);
        float4 bv = *(const float4*)&vb[(size_t)tok * Dn + col0 + bc];
        *(float4*)&Bs[br][bc] = bv;
        __syncthreads();
        #pragma unroll
        for (int kk = 0; kk < 16; kk++) {
            float4 a = *(const float4*)&As[kk][ty << 2];
            float4 b4 = *(const float4*)&Bs[kk][tx << 2];
            float aa[4] = {a.x, a.y, a.z, a.w};
            float bb[4] = {b4.x, b4.y, b4.z, b4.w};
            #pragma unroll
            for (int i = 0; i < 4; i++)
                #pragma unroll
                for (int j = 0; j < 4; j++)
                    acc[i][j] += aa[i] * bb[j];
        }
        __syncthreads();
    }
    float* ob = out + (size_t)b * HWn * Dn;
    #pragma unroll
    for (int i = 0; i < 4; i++) {
        int tok = win_tok(wi, row0 + (ty << 2) + i);
        float4 o = make_float4(acc[i][0], acc[i][1], acc[i][2], acc[i][3]);
        *(float4*)&ob[(size_t)tok * Dn + col0 + (tx << 2)] = o;
    }
}

// ======================================================================
// exact GELU, vectorized
// ======================================================================
__global__ void gelu_kernel(float* __restrict__ x)
{
    size_t i = ((size_t)blockIdx.x * 256 + threadIdx.x) << 2;
    float4 v = *(float4*)&x[i];
    v.x = 0.5f * v.x * (1.0f + erff(v.x * 0.70710678118654752f));
    v.y = 0.5f * v.y * (1.0f + erff(v.y * 0.70710678118654752f));
    v.z = 0.5f * v.z * (1.0f + erff(v.z * 0.70710678118654752f));
    v.w = 0.5f * v.w * (1.0f + erff(v.w * 0.70710678118654752f));
    *(float4*)&x[i] = v;
}

// ======================================================================
// LayerNorm over d=256 (+ optional residual add): one 256-thread block/row
// ======================================================================
__global__ void ln_kernel(const float* __restrict__ x, const float* __restrict__ g,
                          const float* __restrict__ bt, const float* __restrict__ res,
                          float* __restrict__ out)
{
    __shared__ float red[256];
    size_t base = (size_t)blockIdx.x * Dn;
    int t = threadIdx.x;
    float v = x[base + t];
    red[t] = v;
    __syncthreads();
    for (int st = 128; st > 0; st >>= 1) {
        if (t < st) red[t] += red[t + st];
        __syncthreads();
    }
    float mu = red[0] * (1.0f / Dn);
    __syncthreads();
    float d = v - mu;
    red[t] = d * d;
    __syncthreads();
    for (int st = 128; st > 0; st >>= 1) {
        if (t < st) red[t] += red[t + st];
        __syncthreads();
    }
    float var = red[0] * (1.0f / Dn);
    float y = d * rsqrtf(var + 1e-5f) * g[t] + bt[t];
    if (res) y += res[base + t];
    out[base + t] = y;
}

// ======================================================================
extern "C" void kernel_launch(void* const* d_in, const int* in_sizes, int n_in,
                              void* d_out, int out_size)
{
    const float* source = (const float*)d_in[0];
    const float* target = (const float*)d_in[1];
    const float* mask   = (const float*)d_in[2];
    const float* Wq     = (const float*)d_in[3];
    const float* Wk     = (const float*)d_in[4];
    const float* Wv     = (const float*)d_in[5];
    const float* Wm     = (const float*)d_in[6];
    const float* ln1g   = (const float*)d_in[7];
    const float* ln1b   = (const float*)d_in[8];
    const float* W1     = (const float*)d_in[9];
    const float* W2     = (const float*)d_in[10];
    const float* ln2g   = (const float*)d_in[11];
    const float* ln2b   = (const float*)d_in[12];
    float* out = (float*)d_out;

    float *qp, *kp, *vp, *scp, *msgp, *tmpp, *hidp;
    cudaGetSymbolAddress((void**)&qp,   g_q);
    cudaGetSymbolAddress((void**)&kp,   g_k);
    cudaGetSymbolAddress((void**)&vp,   g_v);
    cudaGetSymbolAddress((void**)&scp,  g_sc);
    cudaGetSymbolAddress((void**)&msgp, g_msg);
    cudaGetSymbolAddress((void**)&tmpp, g_tmp);
    cudaGetSymbolAddress((void**)&hidp, g_hid);

    dim3 blk(256);

    // Q/K/V projections: [32768,256] x [256,256]^T
    gemm_nt<<<dim3(Dn/64, Mtot/64), blk>>>(source, Wq, qp, Mtot, Dn, Dn, Dn, 0, 0);
    gemm_nt<<<dim3(Dn/64, Mtot/64), blk>>>(target, Wk, kp, Mtot, Dn, Dn, Dn, 0, 0);
    gemm_nt<<<dim3(Dn/64, Mtot/64), blk>>>(target, Wv, vp, Mtot, Dn, Dn, Dn, 0, 0);

    // attention scores (+scale +mask), softmax, attn @ V (scatter to g_msg)
    scores_kernel<<<dim3(LWn/64, LWn/64, NWn), blk>>>(qp, kp, mask, scp);
    softmax_kernel<<<NWn * LWn, blk>>>(scp);
    attnv_kernel<<<dim3(Dn/64, LWn/64, NWn), blk>>>(scp, vp, msgp);

    // msg @ Wm^T  -> LN1 (into g_msg)
    gemm_nt<<<dim3(Dn/64, Mtot/64), blk>>>(msgp, Wm, tmpp, Mtot, Dn, Dn, Dn, 0, 0);
    ln_kernel<<<Mtot, blk>>>(tmpp, ln1g, ln1b, nullptr, msgp);

    // hid = [source, msg] @ W1^T   (two accumulating K=256 passes over W1[2048,512])
    gemm_nt<<<dim3(DHn/64, Mtot/64), blk>>>(source, W1, hidp, Mtot, DHn, Dn, 2*Dn, 0,  0);
    gemm_nt<<<dim3(DHn/64, Mtot/64), blk>>>(msgp,   W1, hidp, Mtot, DHn, Dn, 2*Dn, Dn, 1);

    // exact GELU
    gelu_kernel<<<(Mtot * DHn) / (256 * 4), blk>>>(hidp);

    // gelu(hid) @ W2^T -> LN2 + residual -> out
    gemm_nt<<<dim3(Dn/64, Mtot/64), blk>>>(hidp, W2, tmpp, Mtot, Dn, DHn, DHn, 0, 0);
    ln_kernel<<<Mtot, blk>>>(tmpp, ln2g, ln2b, source, out);
}

// round 3
// speedup vs baseline: 2.7657x; 2.7657x over previous
#include <cuda_runtime.h>
#include <cuda_bf16.h>
#include <math.h>
#include <stdint.h>

#define Bn 8
#define HWn 4096
#define Dn 256
#define LWn 1024
#define NWn 32
#define DHn 2048
#define Mtot (Bn*HWn)

// ---------------- scratch (device globals; allocation is forbidden) --------
#define AL16 __align__(16)
__device__ AL16 __nv_bfloat16 g_src_h[Mtot*Dn], g_src_l[Mtot*Dn];
__device__ AL16 __nv_bfloat16 g_tgt_h[Mtot*Dn], g_tgt_l[Mtot*Dn];
__device__ AL16 __nv_bfloat16 g_wq_h[Dn*Dn],  g_wq_l[Dn*Dn];
__device__ AL16 __nv_bfloat16 g_wk_h[Dn*Dn],  g_wk_l[Dn*Dn];
__device__ AL16 __nv_bfloat16 g_wv_h[Dn*Dn],  g_wv_l[Dn*Dn];
__device__ AL16 __nv_bfloat16 g_wm_h[Dn*Dn],  g_wm_l[Dn*Dn];
__device__ AL16 __nv_bfloat16 g_w1_h[DHn*2*Dn], g_w1_l[DHn*2*Dn];
__device__ AL16 __nv_bfloat16 g_w2_h[Dn*DHn],  g_w2_l[Dn*DHn];
__device__ AL16 __nv_bfloat16 g_q_h[Mtot*Dn],  g_q_l[Mtot*Dn];
__device__ AL16 __nv_bfloat16 g_k_h[Mtot*Dn],  g_k_l[Mtot*Dn];
__device__ AL16 __nv_bfloat16 g_v_h[Mtot*Dn],  g_v_l[Mtot*Dn];
__device__ AL16 __nv_bfloat16 g_vt_h[Mtot*Dn], g_vt_l[Mtot*Dn];
__device__ AL16 float         g_sc[(size_t)NWn*LWn*LWn];     // also reused as fp32 tmp
__device__ AL16 float         g_tmp[(size_t)Mtot*Dn];
__device__ AL16 __nv_bfloat16 g_at_h[(size_t)NWn*LWn*LWn], g_at_l[(size_t)NWn*LWn*LWn];
__device__ AL16 __nv_bfloat16 g_msg_h[Mtot*Dn],  g_msg_l[Mtot*Dn];
__device__ AL16 __nv_bfloat16 g_msgn_h[Mtot*Dn], g_msgn_l[Mtot*Dn];
__device__ AL16 __nv_bfloat16 g_hid_h[(size_t)Mtot*DHn], g_hid_l[(size_t)Mtot*DHn];

// ---------------- portable PTX helpers (sm_80+ only; no tcgen05) -----------
__device__ __forceinline__ uint32_t smem_u32(const void* p) {
    uint32_t a;
    asm("{ .reg .u64 t; cvta.to.shared.u64 t, %1; cvt.u32.u64 %0, t; }" : "=r"(a) : "l"(p));
    return a;
}
#define SWZ(o) ((o) ^ (((o) >> 3) & 0x70))   // 128B-row XOR swizzle

#define CP16(dst, src) asm volatile("cp.async.cg.shared.global [%0],[%1],16;" \
    :: "r"(dst), "l"(__cvta_generic_to_global(src)) : "memory")
#define CP_COMMIT() asm volatile("cp.async.commit_group;" ::: "memory")
#define CP_WAIT1()  asm volatile("cp.async.wait_group 1;" ::: "memory")
#define CP_WAIT0()  asm volatile("cp.async.wait_group 0;" ::: "memory")

#define LDMX4(r, a) asm volatile("ldmatrix.sync.aligned.m8n8.x4.shared.b16 {%0,%1,%2,%3},[%4];" \
    : "=r"((r)[0]), "=r"((r)[1]), "=r"((r)[2]), "=r"((r)[3]) : "r"(a))

#define MMA(d, a, b) asm volatile( \
    "mma.sync.aligned.m16n8k16.row.col.f32.bf16.bf16.f32 " \
    "{%0,%1,%2,%3},{%4,%5,%6,%7},{%8,%9},{%0,%1,%2,%3};" \
    : "+f"((d)[0]), "+f"((d)[1]), "+f"((d)[2]), "+f"((d)[3]) \
    : "r"((a)[0]), "r"((a)[1]), "r"((a)[2]), "r"((a)[3]), "r"((b)[0]), "r"((b)[1]))

// window-token permutation: roll(-16,-16) + 2x2 window split
__device__ __forceinline__ int win_tok(int wi, int l) {
    int i = l >> 5, j = l & 31;
    int y = (((wi >> 1) << 5) + i + 16) & 63;
    int x = (((wi &  1) << 5) + j + 16) & 63;
    return (y << 6) | x;
}

// ---------------- small kernels ---------------------------------------------
__global__ void cvt_kernel(const float2* __restrict__ in, __nv_bfloat162* __restrict__ h,
                           __nv_bfloat162* __restrict__ l, int n2)
{
    int i = blockIdx.x * 256 + threadIdx.x;
    if (i >= n2) return;
    float2 v = in[i];
    __nv_bfloat16 hx = __float2bfloat16(v.x), hy = __float2bfloat16(v.y);
    __nv_bfloat16 lx = __float2bfloat16(v.x - __bfloat162float(hx));
    __nv_bfloat16 ly = __float2bfloat16(v.y - __bfloat162float(hy));
    h[i] = __halves2bfloat162(hx, hy);
    l[i] = __halves2bfloat162(lx, ly);
}

__global__ void transpose_vt(const __nv_bfloat16* __restrict__ vh, const __nv_bfloat16* __restrict__ vl,
                             __nv_bfloat16* __restrict__ oh, __nv_bfloat16* __restrict__ ol)
{
    __shared__ __nv_bfloat16 th[32][33], tl[32][33];
    int b = blockIdx.z;
    int t0 = blockIdx.x * 32, c0 = blockIdx.y * 32;
    int x = threadIdx.x, y = threadIdx.y;
    for (int i = y; i < 32; i += 8) {
        size_t idx = ((size_t)b * HWn + t0 + i) * Dn + c0 + x;
        th[i][x] = vh[idx]; tl[i][x] = vl[idx];
    }
    __syncthreads();
    for (int i = y; i < 32; i += 8) {
        size_t o = ((size_t)b * Dn + c0 + i) * HWn + t0 + x;
        oh[o] = th[x][i]; ol[o] = tl[x][i];
    }
}

__global__ void softmax_kernel(const float* __restrict__ s, __nv_bfloat16* __restrict__ ah,
                               __nv_bfloat16* __restrict__ al)
{
    __shared__ float red[256];
    size_t base = (size_t)blockIdx.x * LWn;
    int t = threadIdx.x;
    float4 v = *(const float4*)&s[base + (t << 2)];
    red[t] = fmaxf(fmaxf(v.x, v.y), fmaxf(v.z, v.w));
    __syncthreads();
    for (int st = 128; st > 0; st >>= 1) { if (t < st) red[t] = fmaxf(red[t], red[t + st]); __syncthreads(); }
    float rm = red[0]; __syncthreads();
    v.x = __expf(v.x - rm); v.y = __expf(v.y - rm);
    v.z = __expf(v.z - rm); v.w = __expf(v.w - rm);
    red[t] = v.x + v.y + v.z + v.w;
    __syncthreads();
    for (int st = 128; st > 0; st >>= 1) { if (t < st) red[t] += red[t + st]; __syncthreads(); }
    float inv = 1.0f / red[0];
    v.x *= inv; v.y *= inv; v.z *= inv; v.w *= inv;
    __nv_bfloat16 h0=__float2bfloat16(v.x), h1=__float2bfloat16(v.y),
                  h2=__float2bfloat16(v.z), h3=__float2bfloat16(v.w);
    __nv_bfloat16 l0=__float2bfloat16(v.x-__bfloat162float(h0)),
                  l1=__float2bfloat16(v.y-__bfloat162float(h1)),
                  l2=__float2bfloat16(v.z-__bfloat162float(h2)),
                  l3=__float2bfloat16(v.w-__bfloat162float(h3));
    __nv_bfloat162* ph = (__nv_bfloat162*)(ah + base + (t << 2));
    __nv_bfloat162* pl = (__nv_bfloat162*)(al + base + (t << 2));
    ph[0] = __halves2bfloat162(h0, h1); ph[1] = __halves2bfloat162(h2, h3);
    pl[0] = __halves2bfloat162(l0, l1); pl[1] = __halves2bfloat162(l2, l3);
}

// LN over d=256 -> bf16 hi/lo
__global__ void ln_hilo_kernel(const float* __restrict__ x, const float* __restrict__ g,
                               const float* __restrict__ bt,
                               __nv_bfloat16* __restrict__ oh, __nv_bfloat16* __restrict__ ol)
{
    __shared__ float red[256];
    size_t base = (size_t)blockIdx.x * Dn;
    int t = threadIdx.x;
    float v = x[base + t];
    red[t] = v; __syncthreads();
    for (int st = 128; st > 0; st >>= 1) { if (t < st) red[t] += red[t + st]; __syncthreads(); }
    float mu = red[0] * (1.f / Dn); __syncthreads();
    float d = v - mu;
    red[t] = d * d; __syncthreads();
    for (int st = 128; st > 0; st >>= 1) { if (t < st) red[t] += red[t + st]; __syncthreads(); }
    float y = d * rsqrtf(red[0] * (1.f / Dn) + 1e-5f) * g[t] + bt[t];
    __nv_bfloat16 h = __float2bfloat16(y);
    oh[base + t] = h;
    ol[base + t] = __float2bfloat16(y - __bfloat162float(h));
}

// LN over d=256 + residual -> fp32 out
__global__ void ln_res_kernel(const float* __restrict__ x, const float* __restrict__ g,
                              const float* __restrict__ bt, const float* __restrict__ res,
                              float* __restrict__ out)
{
    __shared__ float red[256];
    size_t base = (size_t)blockIdx.x * Dn;
    int t = threadIdx.x;
    float v = x[base + t];
    red[t] = v; __syncthreads();
    for (int st = 128; st > 0; st >>= 1) { if (t < st) red[t] += red[t + st]; __syncthreads(); }
    float mu = red[0] * (1.f / Dn); __syncthreads();
    float d = v - mu;
    red[t] = d * d; __syncthreads();
    for (int st = 128; st > 0; st >>= 1) { if (t < st) red[t] += red[t + st]; __syncthreads(); }
    float y = d * rsqrtf(red[0] * (1.f / Dn) + 1e-5f) * g[t] + bt[t];
    out[base + t] = y + res[base + t];
}

// ---------------- mma.sync GEMM (bf16 hi/lo split, fp32 accumulate) --------
#define V_PROJ   0
#define V_SCORES 1
#define V_ATTNV  2
#define V_WM     3
#define V_W1     4
#define V_W2     5

struct GP {
    const __nv_bfloat16 *Ah, *Al, *Bh, *Bl;
    const __nv_bfloat16 *A2h, *A2l;        // W1 concat second half
    const float *mask;
    float *outf;
    __nv_bfloat16 *outh, *outl;
    int K, Nout;                            // K dim, output row width
};

#define TILEB 16384                        // one 128x64 bf16 tile in smem
#define BUFB  (4*TILEB)                    // Ah,Al,Bh,Bl

template<int V>
__global__ void __launch_bounds__(256, 1)
mma_gemm(GP p)
{
    extern __shared__ char smraw[];
    char* sm = (char*)((((uintptr_t)smraw) + 1023) & ~(uintptr_t)1023);
    uint32_t sb = smem_u32(sm);

    const int tid = threadIdx.x, wid = tid >> 5, lane = tid & 31;
    const int wm = (wid >> 2) * 64;        // warp m offset (2 rows of warps)
    const int wn = (wid & 3) * 32;         // warp n offset (4 cols of warps)

    const int n0 = blockIdx.x * 128;
    const int m0 = blockIdx.y * 128;
    const int bw = blockIdx.z, b = bw >> 2, wi = bw & 3;
    const int KTOT = p.K, NCH = KTOT >> 6;

    float acc[4][4][4];
    #pragma unroll
    for (int i = 0; i < 4; i++)
        #pragma unroll
        for (int j = 0; j < 4; j++)
            #pragma unroll
            for (int e = 0; e < 4; e++) acc[i][j][e] = 0.f;

    // ---- async fill of one k-chunk (64 cols) into buffer (c&1) ----
    auto fill = [&](int c) {
        uint32_t bb = sb + (c & 1) * BUFB;
        int k0 = c << 6;
        #pragma unroll
        for (int it = 0; it < 4; it++) {
            int idx = tid + it * 256;      // 0..1023
            int r = idx >> 3, q = idx & 7; // row, 16B segment
            uint32_t o = SWZ((uint32_t)(r * 128 + q * 16));
            // A tile row
            const __nv_bfloat16 *pah, *pal;
            if constexpr (V == V_SCORES) {
                size_t row = (size_t)b * HWn + win_tok(wi, m0 + r);
                pah = p.Ah + row * Dn + k0 + q * 8; pal = p.Al + row * Dn + k0 + q * 8;
            } else if constexpr (V == V_ATTNV) {
                size_t base = ((size_t)bw * LWn + m0 + r) * (size_t)LWn + k0 + q * 8;
                pah = p.Ah + base; pal = p.Al + base;
            } else if constexpr (V == V_W1) {
                size_t row = (size_t)(m0 + r);
                if (k0 < 256) { pah = p.Ah  + row * 256 + k0 + q * 8;       pal = p.Al  + row * 256 + k0 + q * 8; }
                else          { pah = p.A2h + row * 256 + k0 - 256 + q * 8; pal = p.A2l + row * 256 + k0 - 256 + q * 8; }
            } else {
                size_t row = (size_t)(m0 + r);
                pah = p.Ah + row * (size_t)KTOT + k0 + q * 8;
                pal = p.Al + row * (size_t)KTOT + k0 + q * 8;
            }
            CP16(bb + o, pah);
            CP16(bb + TILEB + o, pal);
            // B tile row
            const __nv_bfloat16 *pbh, *pbl;
            if constexpr (V == V_SCORES) {
                size_t row = (size_t)b * HWn + win_tok(wi, n0 + r);
                pbh = p.Bh + row * Dn + k0 + q * 8; pbl = p.Bl + row * Dn + k0 + q * 8;
            } else if constexpr (V == V_ATTNV) {
                int tok = win_tok(wi, k0 + q * 8);   // 8-aligned: no wrap inside segment
                size_t base = ((size_t)b * Dn + n0 + r) * (size_t)HWn + tok;
                pbh = p.Bh + base; pbl = p.Bl + base;
            } else {
                size_t row = (size_t)(n0 + r);
                pbh = p.Bh + row * (size_t)KTOT + k0 + q * 8;
                pbl = p.Bl + row * (size_t)KTOT + k0 + q * 8;
            }
            CP16(bb + 2 * TILEB + o, pbh);
            CP16(bb + 3 * TILEB + o, pbl);
        }
        CP_COMMIT();
    };

    fill(0);
    for (int c = 0; c < NCH; c++) {
        if (c + 1 < NCH) { fill(c + 1); CP_WAIT1(); } else { CP_WAIT0(); }
        __syncthreads();
        uint32_t bb = sb + (c & 1) * BUFB;
        const uint32_t tAh = bb, tAl = bb + TILEB, tBh = bb + 2 * TILEB, tBl = bb + 3 * TILEB;
        #pragma unroll
        for (int kk = 0; kk < 4; kk++) {
            uint32_t ah[4][4], al[4][4], bh[4][2], bl[4][2];
            int arow = wm + (lane & 15);
            int acol = kk * 16 + (lane >> 4) * 8;
            #pragma unroll
            for (int mf = 0; mf < 4; mf++) {
                uint32_t off = SWZ((uint32_t)((arow + mf * 16) * 128 + acol * 2));
                LDMX4(ah[mf], tAh + off);
                LDMX4(al[mf], tAl + off);
            }
            int brow = wn + ((lane >> 4) << 3) + (lane & 7);
            int bcol = kk * 16 + ((lane >> 3) & 1) * 8;
            #pragma unroll
            for (int np = 0; np < 2; np++) {
                uint32_t off = SWZ((uint32_t)((brow + np * 16) * 128 + bcol * 2));
                uint32_t t4[4];
                LDMX4(t4, tBh + off);
                bh[np*2][0]=t4[0]; bh[np*2][1]=t4[1]; bh[np*2+1][0]=t4[2]; bh[np*2+1][1]=t4[3];
                LDMX4(t4, tBl + off);
                bl[np*2][0]=t4[0]; bl[np*2][1]=t4[1]; bl[np*2+1][0]=t4[2]; bl[np*2+1][1]=t4[3];
            }
            #pragma unroll
            for (int mf = 0; mf < 4; mf++)
                #pragma unroll
                for (int nf = 0; nf < 4; nf++) {
                    MMA(acc[mf][nf], ah[mf], bh[nf]);
                    MMA(acc[mf][nf], ah[mf], bl[nf]);
                    MMA(acc[mf][nf], al[mf], bh[nf]);
                }
        }
        __syncthreads();
    }

    // ---- epilogue: stage fp32 tile in smem, then variant-specific drain ----
    float* stg = (float*)sm;               // [128][130]
    #pragma unroll
    for (int mf = 0; mf < 4; mf++)
        #pragma unroll
        for (int nf = 0; nf < 4; nf++) {
            int r0 = wm + mf * 16 + (lane >> 2);
            int c0 = wn + nf * 8 + (lane & 3) * 2;
            stg[r0 * 130 + c0]     = acc[mf][nf][0];
            stg[r0 * 130 + c0 + 1] = acc[mf][nf][1];
            stg[(r0 + 8) * 130 + c0]     = acc[mf][nf][2];
            stg[(r0 + 8) * 130 + c0 + 1] = acc[mf][nf][3];
        }
    __syncthreads();

    #pragma unroll
    for (int it = 0; it < 16; it++) {
        int e = tid + it * 256;            // 0..4095
        int row = e >> 5;
        int c4 = (e & 31) << 2;
        float4 v = make_float4(stg[row*130+c4], stg[row*130+c4+1], stg[row*130+c4+2], stg[row*130+c4+3]);
        if constexpr (V == V_SCORES) {
            int gl = m0 + row;
            size_t mo = ((size_t)wi * LWn + gl) * LWn + n0 + c4;
            float4 m4 = *(const float4*)&p.mask[mo];
            v.x = v.x * 0.0625f + m4.x; v.y = v.y * 0.0625f + m4.y;
            v.z = v.z * 0.0625f + m4.z; v.w = v.w * 0.0625f + m4.w;
            *(float4*)&p.outf[((size_t)bw * LWn + gl) * LWn + n0 + c4] = v;
        } else if constexpr (V == V_WM || V == V_W2) {
            *(float4*)&p.outf[(size_t)(m0 + row) * Dn + n0 + c4] = v;
        } else {
            if constexpr (V == V_W1) {
                v.x = 0.5f * v.x * (1.f + erff(v.x * 0.70710678118654752f));
                v.y = 0.5f * v.y * (1.f + erff(v.y * 0.70710678118654752f));
                v.z = 0.5f * v.z * (1.f + erff(v.z * 0.70710678118654752f));
                v.w = 0.5f * v.w * (1.f + erff(v.w * 0.70710678118654752f));
            }
            __nv_bfloat16 h0=__float2bfloat16(v.x), h1=__float2bfloat16(v.y),
                          h2=__float2bfloat16(v.z), h3=__float2bfloat16(v.w);
            __nv_bfloat16 l0=__float2bfloat16(v.x-__bfloat162float(h0)),
                          l1=__float2bfloat16(v.y-__bfloat162float(h1)),
                          l2=__float2bfloat16(v.z-__bfloat162float(h2)),
                          l3=__float2bfloat16(v.w-__bfloat162float(h3));
            size_t gi;
            if constexpr (V == V_ATTNV) gi = ((size_t)b * HWn + win_tok(wi, m0 + row)) * Dn + n0 + c4;
            else                        gi = (size_t)(m0 + row) * (size_t)p.Nout + n0 + c4;
            __nv_bfloat162* ph = (__nv_bfloat162*)(p.outh + gi);
            __nv_bfloat162* pl = (__nv_bfloat162*)(p.outl + gi);
            ph[0] = __halves2bfloat162(h0, h1); ph[1] = __halves2bfloat162(h2, h3);
            pl[0] = __halves2bfloat162(l0, l1); pl[1] = __halves2bfloat162(l2, l3);
        }
    }
}

// ---------------- host -------------------------------------------------------
static inline void cvt(const float* in, void* h, void* l, size_t n) {
    int n2 = (int)(n / 2);
    cvt_kernel<<<(n2 + 255) / 256, 256>>>((const float2*)in, (__nv_bfloat162*)h, (__nv_bfloat162*)l, n2);
}

extern "C" void kernel_launch(void* const* d_in, const int* in_sizes, int n_in,
                              void* d_out, int out_size)
{
    const float* source = (const float*)d_in[0];
    const float* target = (const float*)d_in[1];
    const float* mask   = (const float*)d_in[2];
    const float* Wq     = (const float*)d_in[3];
    const float* Wk     = (const float*)d_in[4];
    const float* Wv     = (const float*)d_in[5];
    const float* Wm     = (const float*)d_in[6];
    const float* ln1g   = (const float*)d_in[7];
    const float* ln1b   = (const float*)d_in[8];
    const float* W1     = (const float*)d_in[9];
    const float* W2     = (const float*)d_in[10];
    const float* ln2g   = (const float*)d_in[11];
    const float* ln2b   = (const float*)d_in[12];
    float* out = (float*)d_out;

    #define SYM(p, s) void* p; cudaGetSymbolAddress(&p, s)
    SYM(srch, g_src_h); SYM(srcl, g_src_l); SYM(tgth, g_tgt_h); SYM(tgtl, g_tgt_l);
    SYM(wqh, g_wq_h); SYM(wql, g_wq_l); SYM(wkh, g_wk_h); SYM(wkl, g_wk_l);
    SYM(wvh, g_wv_h); SYM(wvl, g_wv_l); SYM(wmh, g_wm_h); SYM(wml, g_wm_l);
    SYM(w1h, g_w1_h); SYM(w1l, g_w1_l); SYM(w2h, g_w2_h); SYM(w2l, g_w2_l);
    SYM(qh, g_q_h); SYM(ql, g_q_l); SYM(kh, g_k_h); SYM(kl, g_k_l);
    SYM(vh, g_v_h); SYM(vl, g_v_l); SYM(vth, g_vt_h); SYM(vtl, g_vt_l);
    SYM(scp, g_sc); SYM(tmpp, g_tmp); SYM(ath, g_at_h); SYM(atl, g_at_l);
    SYM(msgh, g_msg_h); SYM(msgl, g_msg_l); SYM(msgnh, g_msgn_h); SYM(msgnl, g_msgn_l);
    SYM(hidh, g_hid_h); SYM(hidl, g_hid_l);
    #undef SYM

    const int SMEMZ = 2 * BUFB + 1024;   // 131072 + align pad
    cudaFuncSetAttribute(mma_gemm<V_PROJ>,   cudaFuncAttributeMaxDynamicSharedMemorySize, SMEMZ);
    cudaFuncSetAttribute(mma_gemm<V_SCORES>, cudaFuncAttributeMaxDynamicSharedMemorySize, SMEMZ);
    cudaFuncSetAttribute(mma_gemm<V_ATTNV>,  cudaFuncAttributeMaxDynamicSharedMemorySize, SMEMZ);
    cudaFuncSetAttribute(mma_gemm<V_WM>,     cudaFuncAttributeMaxDynamicSharedMemorySize, SMEMZ);
    cudaFuncSetAttribute(mma_gemm<V_W1>,     cudaFuncAttributeMaxDynamicSharedMemorySize, SMEMZ);
    cudaFuncSetAttribute(mma_gemm<V_W2>,     cudaFuncAttributeMaxDynamicSharedMemorySize, SMEMZ);

    // fp32 -> bf16 hi/lo conversions
    cvt(source, srch, srcl, (size_t)Mtot * Dn);
    cvt(target, tgth, tgtl, (size_t)Mtot * Dn);
    cvt(Wq, wqh, wql, (size_t)Dn * Dn);
    cvt(Wk, wkh, wkl, (size_t)Dn * Dn);
    cvt(Wv, wvh, wvl, (size_t)Dn * Dn);
    cvt(Wm, wmh, wml, (size_t)Dn * Dn);
    cvt(W1, w1h, w1l, (size_t)DHn * 2 * Dn);
    cvt(W2, w2h, w2l, (size_t)Dn * DHn);

    GP p;

    // Q/K/V projections: [32768,256] @ [256,256]^T
    p = GP{}; p.Ah=(const __nv_bfloat16*)srch; p.Al=(const __nv_bfloat16*)srcl;
    p.Bh=(const __nv_bfloat16*)wqh; p.Bl=(const __nv_bfloat16*)wql;
    p.outh=(__nv_bfloat16*)qh; p.outl=(__nv_bfloat16*)ql; p.K=Dn; p.Nout=Dn;
    mma_gemm<V_PROJ><<<dim3(2, Mtot/128, 1), 256, SMEMZ>>>(p);

    p.Ah=(const __nv_bfloat16*)tgth; p.Al=(const __nv_bfloat16*)tgtl;
    p.Bh=(const __nv_bfloat16*)wkh; p.Bl=(const __nv_bfloat16*)wkl;
    p.outh=(__nv_bfloat16*)kh; p.outl=(__nv_bfloat16*)kl;
    mma_gemm<V_PROJ><<<dim3(2, Mtot/128, 1), 256, SMEMZ>>>(p);

    p.Bh=(const __nv_bfloat16*)wvh; p.Bl=(const __nv_bfloat16*)wvl;
    p.outh=(__nv_bfloat16*)vh; p.outl=(__nv_bfloat16*)vl;
    mma_gemm<V_PROJ><<<dim3(2, Mtot/128, 1), 256, SMEMZ>>>(p);

    // V^T for attn@V
    transpose_vt<<<dim3(HWn/32, Dn/32, Bn), dim3(32, 8)>>>(
        (const __nv_bfloat16*)vh, (const __nv_bfloat16*)vl,
        (__nv_bfloat16*)vth, (__nv_bfloat16*)vtl);

    // scores = scale*q@k^T + mask  (window-gathered rows)
    p = GP{}; p.Ah=(const __nv_bfloat16*)qh; p.Al=(const __nv_bfloat16*)ql;
    p.Bh=(const __nv_bfloat16*)kh; p.Bl=(const __nv_bfloat16*)kl;
    p.mask=mask; p.outf=(float*)scp; p.K=Dn;
    mma_gemm<V_SCORES><<<dim3(8, 8, NWn), 256, SMEMZ>>>(p);

    // softmax -> bf16 hi/lo attn
    softmax_kernel<<<NWn * LWn, 256>>>((const float*)scp, (__nv_bfloat16*)ath, (__nv_bfloat16*)atl);

    // attn @ V (scatter rows back through window permutation)
    p = GP{}; p.Ah=(const __nv_bfloat16*)ath; p.Al=(const __nv_bfloat16*)atl;
    p.Bh=(const __nv_bfloat16*)vth; p.Bl=(const __nv_bfloat16*)vtl;
    p.outh=(__nv_bfloat16*)msgh; p.outl=(__nv_bfloat16*)msgl; p.K=LWn; p.Nout=Dn;
    mma_gemm<V_ATTNV><<<dim3(2, 8, NWn), 256, SMEMZ>>>(p);

    // msg @ Wm^T -> fp32 tmp, then LN1 -> bf16 hi/lo
    p = GP{}; p.Ah=(const __nv_bfloat16*)msgh; p.Al=(const __nv_bfloat16*)msgl;
    p.Bh=(const __nv_bfloat16*)wmh; p.Bl=(const __nv_bfloat16*)wml;
    p.outf=(float*)tmpp; p.K=Dn;
    mma_gemm<V_WM><<<dim3(2, Mtot/128, 1), 256, SMEMZ>>>(p);
    ln_hilo_kernel<<<Mtot, 256>>>((const float*)tmpp, ln1g, ln1b,
                                  (__nv_bfloat16*)msgnh, (__nv_bfloat16*)msgnl);

    // hid = gelu([source, msg] @ W1^T) -> bf16 hi/lo
    p = GP{}; p.Ah=(const __nv_bfloat16*)srch; p.Al=(const __nv_bfloat16*)srcl;
    p.A2h=(const __nv_bfloat16*)msgnh; p.A2l=(const __nv_bfloat16*)msgnl;
    p.Bh=(const __nv_bfloat16*)w1h; p.Bl=(const __nv_bfloat16*)w1l;
    p.outh=(__nv_bfloat16*)hidh; p.outl=(__nv_bfloat16*)hidl; p.K=2*Dn; p.Nout=DHn;
    mma_gemm<V_W1><<<dim3(DHn/128, Mtot/128, 1), 256, SMEMZ>>>(p);

    // hid @ W2^T -> fp32 tmp, then out = source + LN2(tmp)
    p = GP{}; p.Ah=(const __nv_bfloat16*)hidh; p.Al=(const __nv_bfloat16*)hidl;
    p.Bh=(const __nv_bfloat16*)w2h; p.Bl=(const __nv_bfloat16*)w2l;
    p.outf=(float*)tmpp; p.K=DHn;
    mma_gemm<V_W2><<<dim3(2, Mtot/128, 1), 256, SMEMZ>>>(p);
    ln_res_kernel<<<Mtot, 256>>>((const float*)tmpp, ln2g, ln2b, source, out);
}

// round 4
// speedup vs baseline: 4.6290x; 1.6737x over previous
#include <cuda_runtime.h>
#include <cuda_fp16.h>
#include <math.h>
#include <stdint.h>

#define Bn 8
#define HWn 4096
#define Dn 256
#define LWn 1024
#define NWn 32
#define DHn 2048
#define Mtot (Bn*HWn)

// ---------------- scratch (device globals; allocation is forbidden) --------
#define AL16 __align__(16)
__device__ AL16 __half g_src[Mtot*Dn];
__device__ AL16 __half g_tgt[Mtot*Dn];
__device__ AL16 __half g_wq[Dn*Dn], g_wk[Dn*Dn], g_wv[Dn*Dn], g_wm[Dn*Dn];
__device__ AL16 __half g_w1[DHn*2*Dn];
__device__ AL16 __half g_w2[Dn*DHn];
__device__ AL16 __half g_q[Mtot*Dn], g_k[Mtot*Dn], g_v[Mtot*Dn], g_vt[Mtot*Dn];
__device__ AL16 float  g_sc[(size_t)NWn*LWn*LWn];
__device__ AL16 float  g_tmp[(size_t)Mtot*Dn];
__device__ AL16 __half g_at[(size_t)NWn*LWn*LWn];
__device__ AL16 __half g_msg[Mtot*Dn];
__device__ AL16 __half g_msgn[Mtot*Dn];
__device__ AL16 __half g_hid[(size_t)Mtot*DHn];

// ---------------- portable PTX helpers (sm_80+ class only) -----------------
__device__ __forceinline__ uint32_t smem_u32(const void* p) {
    uint32_t a;
    asm("{ .reg .u64 t; cvta.to.shared.u64 t, %1; cvt.u32.u64 %0, t; }" : "=r"(a) : "l"(p));
    return a;
}
#define SWZ(o) ((o) ^ (((o) >> 3) & 0x70))   // 128B-row XOR swizzle

#define CP16(dst, src) asm volatile("cp.async.cg.shared.global [%0],[%1],16;" \
    :: "r"(dst), "l"(__cvta_generic_to_global(src)) : "memory")
#define CP_COMMIT() asm volatile("cp.async.commit_group;" ::: "memory")
#define CP_WAIT1()  asm volatile("cp.async.wait_group 1;" ::: "memory")
#define CP_WAIT0()  asm volatile("cp.async.wait_group 0;" ::: "memory")

#define LDMX4(r, a) asm volatile("ldmatrix.sync.aligned.m8n8.x4.shared.b16 {%0,%1,%2,%3},[%4];" \
    : "=r"((r)[0]), "=r"((r)[1]), "=r"((r)[2]), "=r"((r)[3]) : "r"(a))

#define MMA(d, a, b) asm volatile( \
    "mma.sync.aligned.m16n8k16.row.col.f32.f16.f16.f32 " \
    "{%0,%1,%2,%3},{%4,%5,%6,%7},{%8,%9},{%0,%1,%2,%3};" \
    : "+f"((d)[0]), "+f"((d)[1]), "+f"((d)[2]), "+f"((d)[3]) \
    : "r"((a)[0]), "r"((a)[1]), "r"((a)[2]), "r"((a)[3]), "r"((b)[0]), "r"((b)[1]))

// window-token permutation: roll(-16,-16) + 2x2 window split
__device__ __forceinline__ int win_tok(int wi, int l) {
    int i = l >> 5, j = l & 31;
    int y = (((wi >> 1) << 5) + i + 16) & 63;
    int x = (((wi &  1) << 5) + j + 16) & 63;
    return (y << 6) | x;
}

// ---------------- small kernels ---------------------------------------------
__global__ void cvt_kernel(const float2* __restrict__ in, __half2* __restrict__ h, int n2)
{
    int i = blockIdx.x * 256 + threadIdx.x;
    if (i >= n2) return;
    h[i] = __float22half2_rn(in[i]);
}

__global__ void transpose_vt(const __half* __restrict__ v, __half* __restrict__ o)
{
    __shared__ __half t[32][33];
    int b = blockIdx.z;
    int t0 = blockIdx.x * 32, c0 = blockIdx.y * 32;
    int x = threadIdx.x, y = threadIdx.y;
    for (int i = y; i < 32; i += 8)
        t[i][x] = v[((size_t)b * HWn + t0 + i) * Dn + c0 + x];
    __syncthreads();
    for (int i = y; i < 32; i += 8)
        o[((size_t)b * Dn + c0 + i) * HWn + t0 + x] = t[x][i];
}

__global__ void softmax_kernel(const float* __restrict__ s, __half* __restrict__ a)
{
    __shared__ float red[256];
    size_t base = (size_t)blockIdx.x * LWn;
    int t = threadIdx.x;
    float4 v = *(const float4*)&s[base + (t << 2)];
    red[t] = fmaxf(fmaxf(v.x, v.y), fmaxf(v.z, v.w));
    __syncthreads();
    for (int st = 128; st > 0; st >>= 1) { if (t < st) red[t] = fmaxf(red[t], red[t + st]); __syncthreads(); }
    float rm = red[0]; __syncthreads();
    v.x = __expf(v.x - rm); v.y = __expf(v.y - rm);
    v.z = __expf(v.z - rm); v.w = __expf(v.w - rm);
    red[t] = v.x + v.y + v.z + v.w;
    __syncthreads();
    for (int st = 128; st > 0; st >>= 1) { if (t < st) red[t] += red[t + st]; __syncthreads(); }
    float inv = 1.0f / red[0];
    __half2* ph = (__half2*)(a + base + (t << 2));
    ph[0] = __floats2half2_rn(v.x * inv, v.y * inv);
    ph[1] = __floats2half2_rn(v.z * inv, v.w * inv);
}

// LN over d=256 -> fp16
__global__ void ln_h_kernel(const float* __restrict__ x, const float* __restrict__ g,
                            const float* __restrict__ bt, __half* __restrict__ o)
{
    __shared__ float red[256];
    size_t base = (size_t)blockIdx.x * Dn;
    int t = threadIdx.x;
    float v = x[base + t];
    red[t] = v; __syncthreads();
    for (int st = 128; st > 0; st >>= 1) { if (t < st) red[t] += red[t + st]; __syncthreads(); }
    float mu = red[0] * (1.f / Dn); __syncthreads();
    float d = v - mu;
    red[t] = d * d; __syncthreads();
    for (int st = 128; st > 0; st >>= 1) { if (t < st) red[t] += red[t + st]; __syncthreads(); }
    float y = d * rsqrtf(red[0] * (1.f / Dn) + 1e-5f) * g[t] + bt[t];
    o[base + t] = __float2half(y);
}

// LN over d=256 + residual -> fp32 out
__global__ void ln_res_kernel(const float* __restrict__ x, const float* __restrict__ g,
                              const float* __restrict__ bt, const float* __restrict__ res,
                              float* __restrict__ out)
{
    __shared__ float red[256];
    size_t base = (size_t)blockIdx.x * Dn;
    int t = threadIdx.x;
    float v = x[base + t];
    red[t] = v; __syncthreads();
    for (int st = 128; st > 0; st >>= 1) { if (t < st) red[t] += red[t + st]; __syncthreads(); }
    float mu = red[0] * (1.f / Dn); __syncthreads();
    float d = v - mu;
    red[t] = d * d; __syncthreads();
    for (int st = 128; st > 0; st >>= 1) { if (t < st) red[t] += red[t + st]; __syncthreads(); }
    float y = d * rsqrtf(red[0] * (1.f / Dn) + 1e-5f) * g[t] + bt[t];
    out[base + t] = y + res[base + t];
}

// ---------------- mma.sync GEMM (fp16 in, fp32 accumulate) ------------------
#define V_PROJ   0
#define V_SCORES 1
#define V_ATTNV  2
#define V_WM     3
#define V_W1     4
#define V_W2     5

struct GP {
    const __half *A, *B;
    const __half *A2;        // W1 concat second half
    const float *mask;
    float *outf;
    __half *outh;
    int K, Nout;
};

#define TILEB 16384          // one 128x64 fp16 tile
#define BUFB  (2*TILEB)      // A,B

template<int V>
__global__ void __launch_bounds__(256)
mma_gemm(GP p)
{
    extern __shared__ char smraw[];
    char* sm = (char*)((((uintptr_t)smraw) + 1023) & ~(uintptr_t)1023);
    uint32_t sb = smem_u32(sm);

    const int tid = threadIdx.x, wid = tid >> 5, lane = tid & 31;
    const int wm = (wid >> 2) * 64;
    const int wn = (wid & 3) * 32;

    const int n0 = blockIdx.x * 128;
    const int m0 = blockIdx.y * 128;
    const int bw = blockIdx.z, b = bw >> 2, wi = bw & 3;
    const int KTOT = p.K, NCH = KTOT >> 6;

    float acc[4][4][4];
    #pragma unroll
    for (int i = 0; i < 4; i++)
        #pragma unroll
        for (int j = 0; j < 4; j++)
            #pragma unroll
            for (int e = 0; e < 4; e++) acc[i][j][e] = 0.f;

    auto fill = [&](int c) {
        uint32_t bb = sb + (c & 1) * BUFB;
        int k0 = c << 6;
        #pragma unroll
        for (int it = 0; it < 4; it++) {
            int idx = tid + it * 256;
            int r = idx >> 3, q = idx & 7;
            uint32_t o = SWZ((uint32_t)(r * 128 + q * 16));
            const __half *pa;
            if constexpr (V == V_SCORES) {
                size_t row = (size_t)b * HWn + win_tok(wi, m0 + r);
                pa = p.A + row * Dn + k0 + q * 8;
            } else if constexpr (V == V_ATTNV) {
                pa = p.A + ((size_t)bw * LWn + m0 + r) * (size_t)LWn + k0 + q * 8;
            } else if constexpr (V == V_W1) {
                size_t row = (size_t)(m0 + r);
                pa = (k0 < 256) ? p.A + row * 256 + k0 + q * 8
                                : p.A2 + row * 256 + (k0 - 256) + q * 8;
            } else {
                pa = p.A + (size_t)(m0 + r) * (size_t)KTOT + k0 + q * 8;
            }
            CP16(bb + o, pa);
            const __half *pb;
            if constexpr (V == V_SCORES) {
                size_t row = (size_t)b * HWn + win_tok(wi, n0 + r);
                pb = p.B + row * Dn + k0 + q * 8;
            } else if constexpr (V == V_ATTNV) {
                int tok = win_tok(wi, k0 + q * 8);   // 8-aligned: no wrap inside segment
                pb = p.B + ((size_t)b * Dn + n0 + r) * (size_t)HWn + tok;
            } else {
                pb = p.B + (size_t)(n0 + r) * (size_t)KTOT + k0 + q * 8;
            }
            CP16(bb + TILEB + o, pb);
        }
        CP_COMMIT();
    };

    fill(0);
    for (int c = 0; c < NCH; c++) {
        if (c + 1 < NCH) { fill(c + 1); CP_WAIT1(); } else { CP_WAIT0(); }
        __syncthreads();
        uint32_t bb = sb + (c & 1) * BUFB;
        const uint32_t tA = bb, tB = bb + TILEB;
        #pragma unroll
        for (int kk = 0; kk < 4; kk++) {
            uint32_t af[4][4], bf[4][2];
            int arow = wm + (lane & 15);
            int acol = kk * 16 + (lane >> 4) * 8;
            #pragma unroll
            for (int mf = 0; mf < 4; mf++) {
                uint32_t off = SWZ((uint32_t)((arow + mf * 16) * 128 + acol * 2));
                LDMX4(af[mf], tA + off);
            }
            int brow = wn + ((lane >> 4) << 3) + (lane & 7);
            int bcol = kk * 16 + ((lane >> 3) & 1) * 8;
            #pragma unroll
            for (int np = 0; np < 2; np++) {
                uint32_t off = SWZ((uint32_t)((brow + np * 16) * 128 + bcol * 2));
                uint32_t t4[4];
                LDMX4(t4, tB + off);
                bf[np*2][0]=t4[0]; bf[np*2][1]=t4[1]; bf[np*2+1][0]=t4[2]; bf[np*2+1][1]=t4[3];
            }
            #pragma unroll
            for (int mf = 0; mf < 4; mf++)
                #pragma unroll
                for (int nf = 0; nf < 4; nf++)
                    MMA(acc[mf][nf], af[mf], bf[nf]);
        }
        __syncthreads();
    }

    // ---- epilogue: stage fp32 tile in smem, then variant-specific drain ----
    float* stg = (float*)sm;               // [128][130]
    #pragma unroll
    for (int mf = 0; mf < 4; mf++)
        #pragma unroll
        for (int nf = 0; nf < 4; nf++) {
            int r0 = wm + mf * 16 + (lane >> 2);
            int c0 = wn + nf * 8 + (lane & 3) * 2;
            stg[r0 * 130 + c0]     = acc[mf][nf][0];
            stg[r0 * 130 + c0 + 1] = acc[mf][nf][1];
            stg[(r0 + 8) * 130 + c0]     = acc[mf][nf][2];
            stg[(r0 + 8) * 130 + c0 + 1] = acc[mf][nf][3];
        }
    __syncthreads();

    #pragma unroll
    for (int it = 0; it < 16; it++) {
        int e = tid + it * 256;
        int row = e >> 5;
        int c4 = (e & 31) << 2;
        float4 v = make_float4(stg[row*130+c4], stg[row*130+c4+1], stg[row*130+c4+2], stg[row*130+c4+3]);
        if constexpr (V == V_SCORES) {
            int gl = m0 + row;
            size_t mo = ((size_t)wi * LWn + gl) * LWn + n0 + c4;
            float4 m4 = *(const float4*)&p.mask[mo];
            v.x = v.x * 0.0625f + m4.x; v.y = v.y * 0.0625f + m4.y;
            v.z = v.z * 0.0625f + m4.z; v.w = v.w * 0.0625f + m4.w;
            *(float4*)&p.outf[((size_t)bw * LWn + gl) * LWn + n0 + c4] = v;
        } else if constexpr (V == V_WM || V == V_W2) {
            *(float4*)&p.outf[(size_t)(m0 + row) * Dn + n0 + c4] = v;
        } else {
            if constexpr (V == V_W1) {
                v.x = 0.5f * v.x * (1.f + erff(v.x * 0.70710678118654752f));
                v.y = 0.5f * v.y * (1.f + erff(v.y * 0.70710678118654752f));
                v.z = 0.5f * v.z * (1.f + erff(v.z * 0.70710678118654752f));
                v.w = 0.5f * v.w * (1.f + erff(v.w * 0.70710678118654752f));
            }
            size_t gi;
            if constexpr (V == V_ATTNV) gi = ((size_t)b * HWn + win_tok(wi, m0 + row)) * Dn + n0 + c4;
            else                        gi = (size_t)(m0 + row) * (size_t)p.Nout + n0 + c4;
            __half2* ph = (__half2*)(p.outh + gi);
            ph[0] = __floats2half2_rn(v.x, v.y);
            ph[1] = __floats2half2_rn(v.z, v.w);
        }
    }
}

// ---------------- host -------------------------------------------------------
static inline void cvt(const float* in, void* h, size_t n) {
    int n2 = (int)(n / 2);
    cvt_kernel<<<(n2 + 255) / 256, 256>>>((const float2*)in, (__half2*)h, n2);
}

extern "C" void kernel_launch(void* const* d_in, const int* in_sizes, int n_in,
                              void* d_out, int out_size)
{
    const float* source = (const float*)d_in[0];
    const float* target = (const float*)d_in[1];
    const float* mask   = (const float*)d_in[2];
    const float* Wq     = (const float*)d_in[3];
    const float* Wk     = (const float*)d_in[4];
    const float* Wv     = (const float*)d_in[5];
    const float* Wm     = (const float*)d_in[6];
    const float* ln1g   = (const float*)d_in[7];
    const float* ln1b   = (const float*)d_in[8];
    const float* W1     = (const float*)d_in[9];
    const float* W2     = (const float*)d_in[10];
    const float* ln2g   = (const float*)d_in[11];
    const float* ln2b   = (const float*)d_in[12];
    float* out = (float*)d_out;

    #define SYM(p, s) void* p; cudaGetSymbolAddress(&p, s)
    SYM(srcp, g_src); SYM(tgtp, g_tgt);
    SYM(wqp, g_wq); SYM(wkp, g_wk); SYM(wvp, g_wv); SYM(wmp, g_wm);
    SYM(w1p, g_w1); SYM(w2p, g_w2);
    SYM(qp, g_q); SYM(kp, g_k); SYM(vp, g_v); SYM(vtp, g_vt);
    SYM(scp, g_sc); SYM(tmpp, g_tmp); SYM(atp, g_at);
    SYM(msgp, g_msg); SYM(msgnp, g_msgn); SYM(hidp, g_hid);
    #undef SYM

    const int SMEMZ = 2 * BUFB + 2048;   // pipeline 64KB / epilogue 65KB + align
    cudaFuncSetAttribute(mma_gemm<V_PROJ>,   cudaFuncAttributeMaxDynamicSharedMemorySize, SMEMZ);
    cudaFuncSetAttribute(mma_gemm<V_SCORES>, cudaFuncAttributeMaxDynamicSharedMemorySize, SMEMZ);
    cudaFuncSetAttribute(mma_gemm<V_ATTNV>,  cudaFuncAttributeMaxDynamicSharedMemorySize, SMEMZ);
    cudaFuncSetAttribute(mma_gemm<V_WM>,     cudaFuncAttributeMaxDynamicSharedMemorySize, SMEMZ);
    cudaFuncSetAttribute(mma_gemm<V_W1>,     cudaFuncAttributeMaxDynamicSharedMemorySize, SMEMZ);
    cudaFuncSetAttribute(mma_gemm<V_W2>,     cudaFuncAttributeMaxDynamicSharedMemorySize, SMEMZ);

    // fp32 -> fp16 conversions
    cvt(source, srcp, (size_t)Mtot * Dn);
    cvt(target, tgtp, (size_t)Mtot * Dn);
    cvt(Wq, wqp, (size_t)Dn * Dn);
    cvt(Wk, wkp, (size_t)Dn * Dn);
    cvt(Wv, wvp, (size_t)Dn * Dn);
    cvt(Wm, wmp, (size_t)Dn * Dn);
    cvt(W1, w1p, (size_t)DHn * 2 * Dn);
    cvt(W2, w2p, (size_t)Dn * DHn);

    GP p;

    // Q/K/V projections
    p = GP{}; p.A=(const __half*)srcp; p.B=(const __half*)wqp;
    p.outh=(__half*)qp; p.K=Dn; p.Nout=Dn;
    mma_gemm<V_PROJ><<<dim3(2, Mtot/128, 1), 256, SMEMZ>>>(p);

    p.A=(const __half*)tgtp; p.B=(const __half*)wkp; p.outh=(__half*)kp;
    mma_gemm<V_PROJ><<<dim3(2, Mtot/128, 1), 256, SMEMZ>>>(p);

    p.B=(const __half*)wvp; p.outh=(__half*)vp;
    mma_gemm<V_PROJ><<<dim3(2, Mtot/128, 1), 256, SMEMZ>>>(p);

    // V^T for attn@V
    transpose_vt<<<dim3(HWn/32, Dn/32, Bn), dim3(32, 8)>>>((const __half*)vp, (__half*)vtp);

    // scores = scale*q@k^T + mask (window-gathered rows)
    p = GP{}; p.A=(const __half*)qp; p.B=(const __half*)kp;
    p.mask=mask; p.outf=(float*)scp; p.K=Dn;
    mma_gemm<V_SCORES><<<dim3(8, 8, NWn), 256, SMEMZ>>>(p);

    // softmax -> fp16 attn
    softmax_kernel<<<NWn * LWn, 256>>>((const float*)scp, (__half*)atp);

    // attn @ V (scatter rows back through window permutation)
    p = GP{}; p.A=(const __half*)atp; p.B=(const __half*)vtp;
    p.outh=(__half*)msgp; p.K=LWn; p.Nout=Dn;
    mma_gemm<V_ATTNV><<<dim3(2, 8, NWn), 256, SMEMZ>>>(p);

    // msg @ Wm^T -> fp32 tmp, then LN1 -> fp16
    p = GP{}; p.A=(const __half*)msgp; p.B=(const __half*)wmp;
    p.outf=(float*)tmpp; p.K=Dn;
    mma_gemm<V_WM><<<dim3(2, Mtot/128, 1), 256, SMEMZ>>>(p);
    ln_h_kernel<<<Mtot, 256>>>((const float*)tmpp, ln1g, ln1b, (__half*)msgnp);

    // hid = gelu([source, msg] @ W1^T) -> fp16
    p = GP{}; p.A=(const __half*)srcp; p.A2=(const __half*)msgnp;
    p.B=(const __half*)w1p;
    p.outh=(__half*)hidp; p.K=2*Dn; p.Nout=DHn;
    mma_gemm<V_W1><<<dim3(DHn/128, Mtot/128, 1), 256, SMEMZ>>>(p);

    // hid @ W2^T -> fp32 tmp, then out = source + LN2(tmp)
    p = GP{}; p.A=(const __half*)hidp; p.B=(const __half*)w2p;
    p.outf=(float*)tmpp; p.K=DHn;
    mma_gemm<V_W2><<<dim3(2, Mtot/128, 1), 256, SMEMZ>>>(p);
    ln_res_kernel<<<Mtot, 256>>>((const float*)tmpp, ln2g, ln2b, source, out);
}